// round 5
// baseline (speedup 1.0000x reference)
#include <cuda_runtime.h>

// Problem constants
constexpr int B  = 2;
constexpr int S  = 2048;
constexpr int D  = 1024;
constexpr int H  = 16;
constexpr int DK = 64;          // D / H
constexpr int M  = B * S;       // 4096 rows for projection GEMMs

// Scratch (allocation-free rule: __device__ globals)
__device__ float g_q[B * S * D];
__device__ float g_k[B * S * D];
__device__ float g_v[B * S * D];
__device__ float g_o[B * S * D];

// ---------------------------------------------------------------------------
// Kernel 1: QKV projection GEMM.  Y = X @ W + b
// X: [M, D] row-major, W: [D, D] row-major (k-major rows), Y: [M, D]
// blockIdx.z selects which of q/k/v.  64x64 tile, 256 threads, 4x4 micro-tile.
// ---------------------------------------------------------------------------
__global__ __launch_bounds__(256) void qkv_gemm_kernel(
    const float* __restrict__ Xq, const float* __restrict__ Xk, const float* __restrict__ Xv,
    const float* __restrict__ Wq, const float* __restrict__ Wk, const float* __restrict__ Wv,
    const float* __restrict__ bq, const float* __restrict__ bk, const float* __restrict__ bv)
{
    const float* X;
    const float* W;
    const float* bias;
    float* Y;
    if (blockIdx.z == 0)      { X = Xq; W = Wq; bias = bq; Y = g_q; }
    else if (blockIdx.z == 1) { X = Xk; W = Wk; bias = bk; Y = g_k; }
    else                      { X = Xv; W = Wv; bias = bv; Y = g_v; }

    __shared__ __align__(16) float Xs[16][64];   // transposed: Xs[k][row]
    __shared__ __align__(16) float Ws[16][64];   // Ws[k][col]

    const int t  = threadIdx.x;
    const int tx = t & 15;       // 0..15 -> output cols tx*4..tx*4+3
    const int ty = t >> 4;       // 0..15 -> output rows ty*4..ty*4+3
    const int m0 = blockIdx.y * 64;
    const int n0 = blockIdx.x * 64;

    // X-tile load mapping: row 0..63, k-quad 0..3
    const int lrow = t >> 2;        // 0..63
    const int lk   = (t & 3) * 4;   // 0,4,8,12
    // W-tile load mapping
    const int wr = t >> 4;          // 0..15
    const int wc = (t & 15) * 4;    // 0..60

    float acc[4][4];
    #pragma unroll
    for (int i = 0; i < 4; i++)
        #pragma unroll
        for (int j = 0; j < 4; j++) acc[i][j] = 0.f;

    for (int k0 = 0; k0 < D; k0 += 16) {
        float4 xv = *(const float4*)&X[(size_t)(m0 + lrow) * D + k0 + lk];
        Xs[lk + 0][lrow] = xv.x;
        Xs[lk + 1][lrow] = xv.y;
        Xs[lk + 2][lrow] = xv.z;
        Xs[lk + 3][lrow] = xv.w;
        *(float4*)&Ws[wr][wc] = *(const float4*)&W[(size_t)(k0 + wr) * D + n0 + wc];
        __syncthreads();

        #pragma unroll
        for (int kk = 0; kk < 16; kk++) {
            float4 a = *(float4*)&Xs[kk][ty * 4];
            float4 b = *(float4*)&Ws[kk][tx * 4];
            acc[0][0] += a.x * b.x; acc[0][1] += a.x * b.y; acc[0][2] += a.x * b.z; acc[0][3] += a.x * b.w;
            acc[1][0] += a.y * b.x; acc[1][1] += a.y * b.y; acc[1][2] += a.y * b.z; acc[1][3] += a.y * b.w;
            acc[2][0] += a.z * b.x; acc[2][1] += a.z * b.y; acc[2][2] += a.z * b.z; acc[2][3] += a.z * b.w;
            acc[3][0] += a.w * b.x; acc[3][1] += a.w * b.y; acc[3][2] += a.w * b.z; acc[3][3] += a.w * b.w;
        }
        __syncthreads();
    }

    float4 bb = *(const float4*)&bias[n0 + tx * 4];
    #pragma unroll
    for (int i = 0; i < 4; i++) {
        float4 outv;
        outv.x = acc[i][0] + bb.x;
        outv.y = acc[i][1] + bb.y;
        outv.z = acc[i][2] + bb.z;
        outv.w = acc[i][3] + bb.w;
        *(float4*)&Y[(size_t)(m0 + ty * 4 + i) * D + n0 + tx * 4] = outv;
    }
}

// ---------------------------------------------------------------------------
// Kernel 2: flash attention, fp32, online softmax.
// Grid: (S/64 query tiles, B*H).  Block: 256 threads.
// Q tile 64xDK resident; stream K/V in 32-row tiles.
// ---------------------------------------------------------------------------
__global__ __launch_bounds__(256) void attn_kernel()
{
    const int bh = blockIdx.y;
    const int b  = bh / H;
    const int h  = bh % H;
    const int q0 = blockIdx.x * 64;

    __shared__ __align__(16) float Qs[64][68];
    __shared__ float Ks[32][65];
    __shared__ __align__(16) float Vs[32][68];
    __shared__ float Ss[64][33];
    __shared__ float m_s[64], l_s[64], rescale_s[64];

    const int t  = threadIdx.x;
    const int tx = t & 15;   // 0..15
    const int ty = t >> 4;   // 0..15

    const float* qbase = g_q + (size_t)b * S * D + h * DK;
    const float* kbase = g_k + (size_t)b * S * D + h * DK;
    const float* vbase = g_v + (size_t)b * S * D + h * DK;
    float*       obase = g_o + (size_t)b * S * D + h * DK;

    // Load Q tile: 64 rows x 64 dims, 4 float4 per thread
    #pragma unroll
    for (int i = 0; i < 4; i++) {
        int idx = t + i * 256;           // 0..1023
        int row = idx >> 4;              // 0..63
        int d4  = (idx & 15) * 4;        // 0..60
        *(float4*)&Qs[row][d4] = *(const float4*)&qbase[(size_t)(q0 + row) * D + d4];
    }
    if (t < 64) { m_s[t] = -1e30f; l_s[t] = 0.f; }

    float o[4][4];
    #pragma unroll
    for (int i = 0; i < 4; i++)
        #pragma unroll
        for (int j = 0; j < 4; j++) o[i][j] = 0.f;

    __syncthreads();

    for (int kt = 0; kt < S; kt += 32) {
        // Load K (transposed-friendly scalar stores) and V (float4) tiles
        #pragma unroll
        for (int i = 0; i < 2; i++) {
            int idx = t + i * 256;       // 0..511
            int row = idx >> 4;          // 0..31
            int d4  = (idx & 15) * 4;
            float4 kv = *(const float4*)&kbase[(size_t)(kt + row) * D + d4];
            Ks[row][d4 + 0] = kv.x;
            Ks[row][d4 + 1] = kv.y;
            Ks[row][d4 + 2] = kv.z;
            Ks[row][d4 + 3] = kv.w;
            *(float4*)&Vs[row][d4] = *(const float4*)&vbase[(size_t)(kt + row) * D + d4];
        }
        __syncthreads();

        // Phase 1: S(64x32) = Q @ K^T * 0.125 ; thread owns rows 4ty..+3, cols 2tx..+1
        float sacc[4][2];
        #pragma unroll
        for (int i = 0; i < 4; i++) { sacc[i][0] = 0.f; sacc[i][1] = 0.f; }
        #pragma unroll 8
        for (int kk = 0; kk < DK; kk++) {
            float a0 = Qs[4 * ty + 0][kk];
            float a1 = Qs[4 * ty + 1][kk];
            float a2 = Qs[4 * ty + 2][kk];
            float a3 = Qs[4 * ty + 3][kk];
            float b0 = Ks[2 * tx + 0][kk];
            float b1 = Ks[2 * tx + 1][kk];
            sacc[0][0] += a0 * b0; sacc[0][1] += a0 * b1;
            sacc[1][0] += a1 * b0; sacc[1][1] += a1 * b1;
            sacc[2][0] += a2 * b0; sacc[2][1] += a2 * b1;
            sacc[3][0] += a3 * b0; sacc[3][1] += a3 * b1;
        }
        #pragma unroll
        for (int i = 0; i < 4; i++) {
            Ss[4 * ty + i][2 * tx + 0] = sacc[i][0] * 0.125f;
            Ss[4 * ty + i][2 * tx + 1] = sacc[i][1] * 0.125f;
        }
        __syncthreads();

        // Online softmax over this 64x32 tile: 4 lanes per row, 8 cols each
        {
            int row = t >> 2;
            int sub = t & 3;
            float mx = -1e30f;
            #pragma unroll
            for (int c = 0; c < 8; c++) mx = fmaxf(mx, Ss[row][sub * 8 + c]);
            mx = fmaxf(mx, __shfl_xor_sync(0xffffffffu, mx, 1));
            mx = fmaxf(mx, __shfl_xor_sync(0xffffffffu, mx, 2));
            float m_old = m_s[row];
            float m_new = fmaxf(m_old, mx);
            float lsum = 0.f;
            #pragma unroll
            for (int c = 0; c < 8; c++) {
                float p = __expf(Ss[row][sub * 8 + c] - m_new);
                Ss[row][sub * 8 + c] = p;
                lsum += p;
            }
            lsum += __shfl_xor_sync(0xffffffffu, lsum, 1);
            lsum += __shfl_xor_sync(0xffffffffu, lsum, 2);
            if (sub == 0) {
                float rs = __expf(m_old - m_new);
                rescale_s[row] = rs;
                m_s[row] = m_new;
                l_s[row] = l_s[row] * rs + lsum;
            }
        }
        __syncthreads();

        // Phase 2: O = O * rescale + P(64x32) @ V(32x64); thread rows 4ty..+3, cols 4tx..+3
        float r[4];
        #pragma unroll
        for (int i = 0; i < 4; i++) r[i] = rescale_s[4 * ty + i];
        #pragma unroll
        for (int i = 0; i < 4; i++)
            #pragma unroll
            for (int j = 0; j < 4; j++) o[i][j] *= r[i];

        #pragma unroll 8
        for (int kk = 0; kk < 32; kk++) {
            float a0 = Ss[4 * ty + 0][kk];
            float a1 = Ss[4 * ty + 1][kk];
            float a2 = Ss[4 * ty + 2][kk];
            float a3 = Ss[4 * ty + 3][kk];
            float4 bv4 = *(float4*)&Vs[kk][4 * tx];
            o[0][0] += a0 * bv4.x; o[0][1] += a0 * bv4.y; o[0][2] += a0 * bv4.z; o[0][3] += a0 * bv4.w;
            o[1][0] += a1 * bv4.x; o[1][1] += a1 * bv4.y; o[1][2] += a1 * bv4.z; o[1][3] += a1 * bv4.w;
            o[2][0] += a2 * bv4.x; o[2][1] += a2 * bv4.y; o[2][2] += a2 * bv4.z; o[2][3] += a2 * bv4.w;
            o[3][0] += a3 * bv4.x; o[3][1] += a3 * bv4.y; o[3][2] += a3 * bv4.z; o[3][3] += a3 * bv4.w;
        }
        __syncthreads();
    }

    // Finalize: divide by l, write to g_o in [B,S,D] layout (head h -> cols h*64..)
    #pragma unroll
    for (int i = 0; i < 4; i++) {
        float inv = 1.f / l_s[4 * ty + i];
        float4 outv;
        outv.x = o[i][0] * inv;
        outv.y = o[i][1] * inv;
        outv.z = o[i][2] * inv;
        outv.w = o[i][3] * inv;
        *(float4*)&obase[(size_t)(q0 + 4 * ty + i) * D + 4 * tx] = outv;
    }
}

// ---------------------------------------------------------------------------
// Kernel 3: residual add + LayerNorm (eps = 1e-6) + affine.  One block per row.
// ---------------------------------------------------------------------------
__global__ __launch_bounds__(256) void ln_kernel(
    const float* __restrict__ resid,
    const float* __restrict__ gamma,
    const float* __restrict__ beta,
    float* __restrict__ out)
{
    const int row = blockIdx.x;       // 0..4095
    const int t   = threadIdx.x;      // 256 threads, 4 floats each

    float4 o4 = *(const float4*)&g_o[(size_t)row * D + t * 4];
    float4 r4 = *(const float4*)&resid[(size_t)row * D + t * 4];
    float4 y;
    y.x = o4.x + r4.x;
    y.y = o4.y + r4.y;
    y.z = o4.z + r4.z;
    y.w = o4.w + r4.w;

    float s  = y.x + y.y + y.z + y.w;
    float sq = y.x * y.x + y.y * y.y + y.z * y.z + y.w * y.w;

    // warp reduce
    #pragma unroll
    for (int off = 16; off > 0; off >>= 1) {
        s  += __shfl_xor_sync(0xffffffffu, s,  off);
        sq += __shfl_xor_sync(0xffffffffu, sq, off);
    }
    __shared__ float red_s[8], red_q[8], stats[2];
    int wid = t >> 5, lane = t & 31;
    if (lane == 0) { red_s[wid] = s; red_q[wid] = sq; }
    __syncthreads();
    if (t == 0) {
        float ts = 0.f, tq = 0.f;
        #pragma unroll
        for (int i = 0; i < 8; i++) { ts += red_s[i]; tq += red_q[i]; }
        float mu  = ts / (float)D;
        float var = tq / (float)D - mu * mu;
        stats[0] = mu;
        stats[1] = rsqrtf(var + 1e-6f);
    }
    __syncthreads();
    float mu = stats[0], rstd = stats[1];

    float4 g4 = *(const float4*)&gamma[t * 4];
    float4 b4 = *(const float4*)&beta[t * 4];
    float4 outv;
    outv.x = (y.x - mu) * rstd * g4.x + b4.x;
    outv.y = (y.y - mu) * rstd * g4.y + b4.y;
    outv.z = (y.z - mu) * rstd * g4.z + b4.z;
    outv.w = (y.w - mu) * rstd * g4.w + b4.w;
    *(float4*)&out[(size_t)row * D + t * 4] = outv;
}

// ---------------------------------------------------------------------------
extern "C" void kernel_launch(void* const* d_in, const int* in_sizes, int n_in,
                              void* d_out, int out_size)
{
    const float* query = (const float*)d_in[0];
    const float* key_  = (const float*)d_in[1];
    const float* value = (const float*)d_in[2];
    const float* Wq    = (const float*)d_in[3];
    const float* bq    = (const float*)d_in[4];
    const float* Wk    = (const float*)d_in[5];
    const float* bk    = (const float*)d_in[6];
    const float* Wv    = (const float*)d_in[7];
    const float* bv    = (const float*)d_in[8];
    const float* gamma = (const float*)d_in[9];
    const float* beta  = (const float*)d_in[10];
    float* out = (float*)d_out;

    dim3 gproj(D / 64, M / 64, 3);          // (16, 64, 3)
    qkv_gemm_kernel<<<gproj, 256>>>(query, key_, value, Wq, Wk, Wv, bq, bk, bv);

    dim3 gattn(S / 64, B * H);              // (32, 32)
    attn_kernel<<<gattn, 256>>>();

    ln_kernel<<<M, 256>>>(query, gamma, beta, out);
}

// round 7
// speedup vs baseline: 3.4258x; 3.4258x over previous
#include <cuda_runtime.h>
#include <cstdint>

// Problem constants
constexpr int B  = 2;
constexpr int S  = 2048;
constexpr int D  = 1024;
constexpr int H  = 16;
constexpr int DK = 64;
constexpr int M  = B * S;

// Scratch (allocation-free rule: __device__ globals)
__device__ float g_q[M * D];
__device__ float g_k[M * D];
__device__ float g_v[M * D];
__device__ float g_o[M * D];

// ---------------------------------------------------------------------------
// PTX helpers
// ---------------------------------------------------------------------------
__device__ __forceinline__ uint32_t cvt_tf32(float x) {
    uint32_t r;
    asm("cvt.rna.tf32.f32 %0, %1;" : "=r"(r) : "f"(x));
    return r;
}

__device__ __forceinline__ void mma_tf32(float c[4],
                                         uint32_t a0, uint32_t a1, uint32_t a2, uint32_t a3,
                                         uint32_t b0, uint32_t b1) {
    asm volatile(
        "mma.sync.aligned.m16n8k8.row.col.f32.tf32.tf32.f32 "
        "{%0,%1,%2,%3}, {%4,%5,%6,%7}, {%8,%9}, {%0,%1,%2,%3};\n"
        : "+f"(c[0]), "+f"(c[1]), "+f"(c[2]), "+f"(c[3])
        : "r"(a0), "r"(a1), "r"(a2), "r"(a3), "r"(b0), "r"(b1));
}

__device__ __forceinline__ void cp16(void* smem_ptr, const void* gptr) {
    uint32_t s = (uint32_t)__cvta_generic_to_shared(smem_ptr);
    asm volatile("cp.async.cg.shared.global [%0], [%1], 16;\n" :: "r"(s), "l"(gptr));
}
__device__ __forceinline__ void cp_commit() { asm volatile("cp.async.commit_group;\n"); }
template <int N>
__device__ __forceinline__ void cp_wait() { asm volatile("cp.async.wait_group %0;\n" :: "n"(N)); }

// ---------------------------------------------------------------------------
// Kernel 1: QKV projection GEMM on tensor cores (tf32).
// Block tile 128x128, K-step 16, double-buffered cp.async.
// 256 threads = 8 warps (4 x 2); warp tile 32x64 (2 m-tiles x 8 n-tiles).
// ---------------------------------------------------------------------------
constexpr int AST = 20;    // A smem k-stride pad (banks 4m+k conflict-free)
constexpr int BST = 136;   // B smem n-stride pad (banks 8k+n conflict-free)

__global__ __launch_bounds__(256, 2) void qkv_gemm_tc(
    const float* __restrict__ Xq, const float* __restrict__ Xk, const float* __restrict__ Xv,
    const float* __restrict__ Wq, const float* __restrict__ Wk, const float* __restrict__ Wv,
    const float* __restrict__ bq, const float* __restrict__ bk, const float* __restrict__ bv)
{
    const float* X; const float* W; const float* bias; float* Y;
    if (blockIdx.z == 0)      { X = Xq; W = Wq; bias = bq; Y = g_q; }
    else if (blockIdx.z == 1) { X = Xk; W = Wk; bias = bk; Y = g_k; }
    else                      { X = Xv; W = Wv; bias = bv; Y = g_v; }

    __shared__ float As[2][128 * AST];
    __shared__ float Bs[2][16 * BST];

    const int t    = threadIdx.x;
    const int lane = t & 31;
    const int warp = t >> 5;
    const int wm   = (warp >> 1) * 32;     // warp m offset within block tile
    const int wn   = (warp & 1) * 64;      // warp n offset
    const int g    = lane >> 2;            // groupID 0..7
    const int tg   = lane & 3;             // thread-in-group 0..3
    const int m0   = blockIdx.y * 128;
    const int n0   = blockIdx.x * 128;

    float acc[2][8][4] = {};

    auto load_tiles = [&](int k0, int buf) {
        #pragma unroll
        for (int i = 0; i < 2; i++) {
            int f = t + i * 256;                 // 0..511
            int r = f >> 2, c4 = (f & 3) * 4;    // A: 128 rows x 16 cols
            cp16(&As[buf][r * AST + c4], &X[(size_t)(m0 + r) * D + k0 + c4]);
        }
        #pragma unroll
        for (int i = 0; i < 2; i++) {
            int f = t + i * 256;
            int r = f >> 5, c4 = (f & 31) * 4;   // B: 16 rows x 128 cols
            cp16(&Bs[buf][r * BST + c4], &W[(size_t)(k0 + r) * D + n0 + c4]);
        }
        cp_commit();
    };

    constexpr int KT = D / 16;   // 64 k-steps
    load_tiles(0, 0);

    for (int kt = 0; kt < KT; kt++) {
        const int buf = kt & 1;
        if (kt + 1 < KT) {
            load_tiles((kt + 1) * 16, buf ^ 1);
            cp_wait<1>();
        } else {
            cp_wait<0>();
        }
        __syncthreads();

        #pragma unroll
        for (int k8 = 0; k8 < 16; k8 += 8) {
            uint32_t a[2][4];
            #pragma unroll
            for (int mt = 0; mt < 2; mt++) {
                const int r0 = wm + mt * 16 + g;
                a[mt][0] = cvt_tf32(As[buf][r0 * AST + k8 + tg]);
                a[mt][1] = cvt_tf32(As[buf][(r0 + 8) * AST + k8 + tg]);
                a[mt][2] = cvt_tf32(As[buf][r0 * AST + k8 + tg + 4]);
                a[mt][3] = cvt_tf32(As[buf][(r0 + 8) * AST + k8 + tg + 4]);
            }
            #pragma unroll
            for (int nt = 0; nt < 8; nt++) {
                const int col = wn + nt * 8 + g;
                uint32_t b0 = cvt_tf32(Bs[buf][(k8 + tg) * BST + col]);
                uint32_t b1 = cvt_tf32(Bs[buf][(k8 + tg + 4) * BST + col]);
                mma_tf32(acc[0][nt], a[0][0], a[0][1], a[0][2], a[0][3], b0, b1);
                mma_tf32(acc[1][nt], a[1][0], a[1][1], a[1][2], a[1][3], b0, b1);
            }
        }
        __syncthreads();
    }

    // Epilogue: + bias, write float2 pairs
    #pragma unroll
    for (int nt = 0; nt < 8; nt++) {
        const int col = n0 + wn + nt * 8 + 2 * tg;
        const float bv0 = bias[col];
        const float bv1 = bias[col + 1];
        #pragma unroll
        for (int mt = 0; mt < 2; mt++) {
            const int row = m0 + wm + mt * 16 + g;
            float2 v0 = make_float2(acc[mt][nt][0] + bv0, acc[mt][nt][1] + bv1);
            float2 v1 = make_float2(acc[mt][nt][2] + bv0, acc[mt][nt][3] + bv1);
            *(float2*)&Y[(size_t)row * D + col] = v0;
            *(float2*)&Y[(size_t)(row + 8) * D + col] = v1;
        }
    }
}

// ---------------------------------------------------------------------------
// Kernel 2: flash attention on tensor cores (tf32), online softmax in C-frags.
// Grid (S/64, B*H), 128 threads = 4 warps; warp owns 16 query rows.
// Q fragments register-resident; K/V tiles double-buffered via cp.async.
// ---------------------------------------------------------------------------
constexpr int QST = 68;   // P smem stride (banks 4m+k conflict-free)
constexpr int KST = 68;   // K smem stride
constexpr int VST = 72;   // V smem stride (banks 8k+n conflict-free)
constexpr int STAGE = 64 * KST + 64 * VST;                 // floats per stage
constexpr int ATTN_SMEM = (64 * QST + 2 * STAGE) * 4;      // 89088 bytes

__global__ __launch_bounds__(128) void attn_tc()
{
    extern __shared__ float sm[];
    float* Ps     = sm;               // 64 x QST, warp-private row blocks
    float* stage0 = sm + 64 * QST;

    const int t    = threadIdx.x;
    const int lane = t & 31;
    const int warp = t >> 5;
    const int g    = lane >> 2;
    const int tg   = lane & 3;

    const int bh = blockIdx.y;
    const int b  = bh / H;
    const int h  = bh % H;
    const int q0 = blockIdx.x * 64;

    const float* qb = g_q + (size_t)b * S * D + h * DK;
    const float* kb = g_k + (size_t)b * S * D + h * DK;
    const float* vb = g_v + (size_t)b * S * D + h * DK;
    float*       ob = g_o + (size_t)b * S * D + h * DK;

    // Q fragments, loaded once straight from gmem (A operand, m16 x k64)
    const int qrow = q0 + warp * 16 + g;
    const float* qr0 = qb + (size_t)qrow * D;
    const float* qr8 = qb + (size_t)(qrow + 8) * D;
    uint32_t qf[8][4];
    #pragma unroll
    for (int k8 = 0; k8 < 8; k8++) {
        qf[k8][0] = cvt_tf32(qr0[k8 * 8 + tg]);
        qf[k8][1] = cvt_tf32(qr8[k8 * 8 + tg]);
        qf[k8][2] = cvt_tf32(qr0[k8 * 8 + tg + 4]);
        qf[k8][3] = cvt_tf32(qr8[k8 * 8 + tg + 4]);
    }

    float m0v = -1e30f, m1v = -1e30f, l0 = 0.f, l1 = 0.f;
    float o[8][4] = {};

    auto load_kv = [&](int kt, int st) {
        float* K = stage0 + st * STAGE;
        float* V = K + 64 * KST;
        #pragma unroll
        for (int i = 0; i < 8; i++) {
            int f = t + i * 128;              // 0..1023
            int r = f >> 4;                   // 0..63
            int c4 = (f & 15) * 4;            // 0..60
            cp16(&K[r * KST + c4], &kb[(size_t)(kt + r) * D + c4]);
            cp16(&V[r * VST + c4], &vb[(size_t)(kt + r) * D + c4]);
        }
        cp_commit();
    };

    constexpr int NT = S / 64;   // 32 key tiles
    load_kv(0, 0);

    for (int it = 0; it < NT; it++) {
        const int st = it & 1;
        if (it + 1 < NT) {
            load_kv((it + 1) * 64, st ^ 1);
            cp_wait<1>();
        } else {
            cp_wait<0>();
        }
        __syncthreads();

        float* K = stage0 + st * STAGE;
        float* V = K + 64 * KST;

        // Phase 1: scores (16 q-rows x 64 keys per warp), B frags from K tile
        float sc[8][4] = {};
        #pragma unroll
        for (int k8 = 0; k8 < 8; k8++) {
            #pragma unroll
            for (int nt = 0; nt < 8; nt++) {
                uint32_t b0 = cvt_tf32(K[(nt * 8 + g) * KST + k8 * 8 + tg]);
                uint32_t b1 = cvt_tf32(K[(nt * 8 + g) * KST + k8 * 8 + tg + 4]);
                mma_tf32(sc[nt], qf[k8][0], qf[k8][1], qf[k8][2], qf[k8][3], b0, b1);
            }
        }

        // Scale + online softmax in register fragments
        float mx0 = -1e30f, mx1 = -1e30f;
        #pragma unroll
        for (int nt = 0; nt < 8; nt++) {
            #pragma unroll
            for (int j = 0; j < 4; j++) sc[nt][j] *= 0.125f;
            mx0 = fmaxf(mx0, fmaxf(sc[nt][0], sc[nt][1]));
            mx1 = fmaxf(mx1, fmaxf(sc[nt][2], sc[nt][3]));
        }
        mx0 = fmaxf(mx0, __shfl_xor_sync(0xffffffffu, mx0, 1));
        mx0 = fmaxf(mx0, __shfl_xor_sync(0xffffffffu, mx0, 2));
        mx1 = fmaxf(mx1, __shfl_xor_sync(0xffffffffu, mx1, 1));
        mx1 = fmaxf(mx1, __shfl_xor_sync(0xffffffffu, mx1, 2));

        const float mn0 = fmaxf(m0v, mx0);
        const float mn1 = fmaxf(m1v, mx1);
        const float rs0 = __expf(m0v - mn0);
        const float rs1 = __expf(m1v - mn1);
        m0v = mn0; m1v = mn1;

        const int r0 = warp * 16 + g;
        float s0 = 0.f, s1 = 0.f;
        #pragma unroll
        for (int nt = 0; nt < 8; nt++) {
            float p0 = __expf(sc[nt][0] - mn0);
            float p1 = __expf(sc[nt][1] - mn0);
            float p2 = __expf(sc[nt][2] - mn1);
            float p3 = __expf(sc[nt][3] - mn1);
            s0 += p0 + p1;
            s1 += p2 + p3;
            const int col = nt * 8 + 2 * tg;
            // store tf32-rounded bits (directly consumable as mma A operand)
            float2 w0 = make_float2(__uint_as_float(cvt_tf32(p0)), __uint_as_float(cvt_tf32(p1)));
            float2 w1 = make_float2(__uint_as_float(cvt_tf32(p2)), __uint_as_float(cvt_tf32(p3)));
            *(float2*)&Ps[r0 * QST + col] = w0;
            *(float2*)&Ps[(r0 + 8) * QST + col] = w1;
        }
        s0 += __shfl_xor_sync(0xffffffffu, s0, 1);
        s0 += __shfl_xor_sync(0xffffffffu, s0, 2);
        s1 += __shfl_xor_sync(0xffffffffu, s1, 1);
        s1 += __shfl_xor_sync(0xffffffffu, s1, 2);
        l0 = l0 * rs0 + s0;
        l1 = l1 * rs1 + s1;

        // Rescale O accumulators
        #pragma unroll
        for (int nt = 0; nt < 8; nt++) {
            o[nt][0] *= rs0; o[nt][1] *= rs0;
            o[nt][2] *= rs1; o[nt][3] *= rs1;
        }
        __syncwarp();   // P rows are warp-private; warp-scope visibility suffices

        // Phase 2: O += P @ V   (A frags from Ps, B frags from V tile)
        #pragma unroll
        for (int k8 = 0; k8 < 8; k8++) {
            uint32_t a0 = __float_as_uint(Ps[r0 * QST + k8 * 8 + tg]);
            uint32_t a1 = __float_as_uint(Ps[(r0 + 8) * QST + k8 * 8 + tg]);
            uint32_t a2 = __float_as_uint(Ps[r0 * QST + k8 * 8 + tg + 4]);
            uint32_t a3 = __float_as_uint(Ps[(r0 + 8) * QST + k8 * 8 + tg + 4]);
            #pragma unroll
            for (int nt = 0; nt < 8; nt++) {
                uint32_t b0 = cvt_tf32(V[(k8 * 8 + tg) * VST + nt * 8 + g]);
                uint32_t b1 = cvt_tf32(V[(k8 * 8 + tg + 4) * VST + nt * 8 + g]);
                mma_tf32(o[nt], a0, a1, a2, a3, b0, b1);
            }
        }
        __syncthreads();   // protect K/V stage buffer before next prefetch overwrites
    }

    // Epilogue: normalize by l, write out
    const float inv0 = 1.f / l0;
    const float inv1 = 1.f / l1;
    const int row0 = q0 + warp * 16 + g;
    #pragma unroll
    for (int nt = 0; nt < 8; nt++) {
        const int col = nt * 8 + 2 * tg;
        float2 v0 = make_float2(o[nt][0] * inv0, o[nt][1] * inv0);
        float2 v1 = make_float2(o[nt][2] * inv1, o[nt][3] * inv1);
        *(float2*)&ob[(size_t)row0 * D + col] = v0;
        *(float2*)&ob[(size_t)(row0 + 8) * D + col] = v1;
    }
}

// ---------------------------------------------------------------------------
// Kernel 3: residual add + LayerNorm (eps = 1e-6) + affine.  One block per row.
// ---------------------------------------------------------------------------
__global__ __launch_bounds__(256) void ln_kernel(
    const float* __restrict__ resid,
    const float* __restrict__ gamma,
    const float* __restrict__ beta,
    float* __restrict__ out)
{
    const int row = blockIdx.x;
    const int t   = threadIdx.x;

    float4 o4 = *(const float4*)&g_o[(size_t)row * D + t * 4];
    float4 r4 = *(const float4*)&resid[(size_t)row * D + t * 4];
    float4 y;
    y.x = o4.x + r4.x;
    y.y = o4.y + r4.y;
    y.z = o4.z + r4.z;
    y.w = o4.w + r4.w;

    float s  = y.x + y.y + y.z + y.w;
    float sq = y.x * y.x + y.y * y.y + y.z * y.z + y.w * y.w;

    #pragma unroll
    for (int off = 16; off > 0; off >>= 1) {
        s  += __shfl_xor_sync(0xffffffffu, s,  off);
        sq += __shfl_xor_sync(0xffffffffu, sq, off);
    }
    __shared__ float red_s[8], red_q[8], stats[2];
    int wid = t >> 5, lane = t & 31;
    if (lane == 0) { red_s[wid] = s; red_q[wid] = sq; }
    __syncthreads();
    if (t == 0) {
        float ts = 0.f, tq = 0.f;
        #pragma unroll
        for (int i = 0; i < 8; i++) { ts += red_s[i]; tq += red_q[i]; }
        float mu  = ts / (float)D;
        float var = tq / (float)D - mu * mu;
        stats[0] = mu;
        stats[1] = rsqrtf(var + 1e-6f);
    }
    __syncthreads();
    float mu = stats[0], rstd = stats[1];

    float4 g4 = *(const float4*)&gamma[t * 4];
    float4 b4 = *(const float4*)&beta[t * 4];
    float4 outv;
    outv.x = (y.x - mu) * rstd * g4.x + b4.x;
    outv.y = (y.y - mu) * rstd * g4.y + b4.y;
    outv.z = (y.z - mu) * rstd * g4.z + b4.z;
    outv.w = (y.w - mu) * rstd * g4.w + b4.w;
    *(float4*)&out[(size_t)row * D + t * 4] = outv;
}

// ---------------------------------------------------------------------------
extern "C" void kernel_launch(void* const* d_in, const int* in_sizes, int n_in,
                              void* d_out, int out_size)
{
    const float* query = (const float*)d_in[0];
    const float* key_  = (const float*)d_in[1];
    const float* value = (const float*)d_in[2];
    const float* Wq    = (const float*)d_in[3];
    const float* bq    = (const float*)d_in[4];
    const float* Wk    = (const float*)d_in[5];
    const float* bk    = (const float*)d_in[6];
    const float* Wv    = (const float*)d_in[7];
    const float* bv    = (const float*)d_in[8];
    const float* gamma = (const float*)d_in[9];
    const float* beta  = (const float*)d_in[10];
    float* out = (float*)d_out;

    // Opt-in to >48KB dynamic smem for the attention kernel (idempotent; no alloc)
    cudaFuncSetAttribute(attn_tc, cudaFuncAttributeMaxDynamicSharedMemorySize, ATTN_SMEM);

    dim3 gproj(D / 128, M / 128, 3);        // (8, 32, 3)
    qkv_gemm_tc<<<gproj, 256>>>(query, key_, value, Wq, Wk, Wv, bq, bk, bv);

    dim3 gattn(S / 64, B * H);              // (32, 32)
    attn_tc<<<gattn, 128, ATTN_SMEM>>>();

    ln_kernel<<<M, 256>>>(query, gamma, beta, out);
}

// round 11
// speedup vs baseline: 3.8716x; 1.1301x over previous
#include <cuda_runtime.h>
#include <cstdint>

// Problem constants
constexpr int B  = 2;
constexpr int S  = 2048;
constexpr int D  = 1024;
constexpr int H  = 16;
constexpr int DK = 64;
constexpr int M  = B * S;

// Scratch (allocation-free rule: __device__ globals)
__device__ float g_q[M * D];
__device__ float g_k[M * D];
__device__ float g_v[M * D];
__device__ float g_o[M * D];

// ---------------------------------------------------------------------------
// PTX helpers
// ---------------------------------------------------------------------------
__device__ __forceinline__ void mma_tf32(float c[4],
                                         uint32_t a0, uint32_t a1, uint32_t a2, uint32_t a3,
                                         uint32_t b0, uint32_t b1) {
    asm volatile(
        "mma.sync.aligned.m16n8k8.row.col.f32.tf32.tf32.f32 "
        "{%0,%1,%2,%3}, {%4,%5,%6,%7}, {%8,%9}, {%0,%1,%2,%3};\n"
        : "+f"(c[0]), "+f"(c[1]), "+f"(c[2]), "+f"(c[3])
        : "r"(a0), "r"(a1), "r"(a2), "r"(a3), "r"(b0), "r"(b1));
}

__device__ __forceinline__ void cp16(void* smem_ptr, const void* gptr) {
    uint32_t s = (uint32_t)__cvta_generic_to_shared(smem_ptr);
    asm volatile("cp.async.cg.shared.global [%0], [%1], 16;\n" :: "r"(s), "l"(gptr));
}
__device__ __forceinline__ void cp_commit() { asm volatile("cp.async.commit_group;\n"); }
template <int N>
__device__ __forceinline__ void cp_wait() { asm volatile("cp.async.wait_group %0;\n" :: "n"(N)); }

// Raw fp32 bits as tf32 operand (HMMA.TF32 truncates low mantissa bits in HW)
__device__ __forceinline__ uint32_t f2u(float x) { return __float_as_uint(x); }

// ---------------------------------------------------------------------------
// Kernel 1: QKV projection GEMM on tensor cores (tf32).
// Block tile 128x128, K-step 32, double-buffered cp.async (dynamic smem).
// 256 threads = 8 warps (4 x 2); warp tile 32x64 (2 m-tiles x 8 n-tiles).
// ---------------------------------------------------------------------------
constexpr int KS  = 32;
constexpr int AST = 36;    // A smem k-stride pad: (36g+tg)%32 = (4g+tg) -> conflict-free
constexpr int BST = 136;   // B smem n-stride pad: (136tg+g)%32 = (8tg+g) -> conflict-free
constexpr int ASTAGE = 128 * AST;         // 4608 floats
constexpr int BSTAGE = KS * BST;          // 4352 floats
constexpr int QKV_STAGE = ASTAGE + BSTAGE;
constexpr int QKV_SMEM  = 2 * QKV_STAGE * 4;   // 71680 bytes

__global__ __launch_bounds__(256, 2) void qkv_gemm_tc(
    const float* __restrict__ Xq, const float* __restrict__ Xk, const float* __restrict__ Xv,
    const float* __restrict__ Wq, const float* __restrict__ Wk, const float* __restrict__ Wv,
    const float* __restrict__ bq, const float* __restrict__ bk, const float* __restrict__ bv)
{
    const float* X; const float* W; const float* bias; float* Y;
    if (blockIdx.z == 0)      { X = Xq; W = Wq; bias = bq; Y = g_q; }
    else if (blockIdx.z == 1) { X = Xk; W = Wk; bias = bk; Y = g_k; }
    else                      { X = Xv; W = Wv; bias = bv; Y = g_v; }

    extern __shared__ float qsm[];

    const int t    = threadIdx.x;
    const int lane = t & 31;
    const int warp = t >> 5;
    const int wm   = (warp >> 1) * 32;     // warp m offset within block tile
    const int wn   = (warp & 1) * 64;      // warp n offset
    const int g    = lane >> 2;            // groupID 0..7
    const int tg   = lane & 3;             // thread-in-group 0..3
    const int m0   = blockIdx.y * 128;
    const int n0   = blockIdx.x * 128;

    float acc[2][8][4] = {};

    auto load_tiles = [&](int k0, int buf) {
        float* As = qsm + buf * QKV_STAGE;
        float* Bs = As + ASTAGE;
        #pragma unroll
        for (int i = 0; i < 4; i++) {
            int f = t + i * 256;                 // 0..1023
            int r = f >> 3, c4 = (f & 7) * 4;    // A: 128 rows x 32 cols
            cp16(&As[r * AST + c4], &X[(size_t)(m0 + r) * D + k0 + c4]);
        }
        #pragma unroll
        for (int i = 0; i < 4; i++) {
            int f = t + i * 256;
            int r = f >> 5, c4 = (f & 31) * 4;   // B: 32 rows x 128 cols
            cp16(&Bs[r * BST + c4], &W[(size_t)(k0 + r) * D + n0 + c4]);
        }
        cp_commit();
    };

    constexpr int KT = D / KS;   // 32 k-steps
    load_tiles(0, 0);

    for (int kt = 0; kt < KT; kt++) {
        const int buf = kt & 1;
        if (kt + 1 < KT) {
            load_tiles((kt + 1) * KS, buf ^ 1);
            cp_wait<1>();
        } else {
            cp_wait<0>();
        }
        __syncthreads();

        const float* As = qsm + buf * QKV_STAGE;
        const float* Bs = As + ASTAGE;

        #pragma unroll
        for (int k8 = 0; k8 < KS; k8 += 8) {
            uint32_t a[2][4];
            #pragma unroll
            for (int mt = 0; mt < 2; mt++) {
                const int r0 = wm + mt * 16 + g;
                a[mt][0] = f2u(As[r0 * AST + k8 + tg]);
                a[mt][1] = f2u(As[(r0 + 8) * AST + k8 + tg]);
                a[mt][2] = f2u(As[r0 * AST + k8 + tg + 4]);
                a[mt][3] = f2u(As[(r0 + 8) * AST + k8 + tg + 4]);
            }
            #pragma unroll
            for (int nt = 0; nt < 8; nt++) {
                const int col = wn + nt * 8 + g;
                uint32_t b0 = f2u(Bs[(k8 + tg) * BST + col]);
                uint32_t b1 = f2u(Bs[(k8 + tg + 4) * BST + col]);
                mma_tf32(acc[0][nt], a[0][0], a[0][1], a[0][2], a[0][3], b0, b1);
                mma_tf32(acc[1][nt], a[1][0], a[1][1], a[1][2], a[1][3], b0, b1);
            }
        }
        __syncthreads();
    }

    // Epilogue: + bias, write float2 pairs
    #pragma unroll
    for (int nt = 0; nt < 8; nt++) {
        const int col = n0 + wn + nt * 8 + 2 * tg;
        const float bv0 = bias[col];
        const float bv1 = bias[col + 1];
        #pragma unroll
        for (int mt = 0; mt < 2; mt++) {
            const int row = m0 + wm + mt * 16 + g;
            float2 v0 = make_float2(acc[mt][nt][0] + bv0, acc[mt][nt][1] + bv1);
            float2 v1 = make_float2(acc[mt][nt][2] + bv0, acc[mt][nt][3] + bv1);
            *(float2*)&Y[(size_t)row * D + col] = v0;
            *(float2*)&Y[(size_t)(row + 8) * D + col] = v1;
        }
    }
}

// ---------------------------------------------------------------------------
// Kernel 2: flash attention on tensor cores (tf32), online softmax in C-frags.
// Grid (S/64, B*H), 128 threads = 4 warps; warp owns 16 query rows.
// Q fragments register-resident; K/V tiles double-buffered via cp.async.
// ---------------------------------------------------------------------------
constexpr int QST = 68;   // P smem stride
constexpr int KST = 68;   // K smem stride
constexpr int VST = 72;   // V smem stride
constexpr int STAGE = 64 * KST + 64 * VST;                 // floats per stage
constexpr int ATTN_SMEM = (64 * QST + 2 * STAGE) * 4;      // 89088 bytes

__global__ __launch_bounds__(128) void attn_tc()
{
    extern __shared__ float sm[];
    float* Ps     = sm;               // 64 x QST, warp-private row blocks
    float* stage0 = sm + 64 * QST;

    const int t    = threadIdx.x;
    const int lane = t & 31;
    const int warp = t >> 5;
    const int g    = lane >> 2;
    const int tg   = lane & 3;

    const int bh = blockIdx.y;
    const int b  = bh / H;
    const int h  = bh % H;
    const int q0 = blockIdx.x * 64;

    const float* qb = g_q + (size_t)b * S * D + h * DK;
    const float* kb = g_k + (size_t)b * S * D + h * DK;
    const float* vb = g_v + (size_t)b * S * D + h * DK;
    float*       ob = g_o + (size_t)b * S * D + h * DK;

    // Q fragments, loaded once straight from gmem (A operand, m16 x k64)
    const int qrow = q0 + warp * 16 + g;
    const float* qr0 = qb + (size_t)qrow * D;
    const float* qr8 = qb + (size_t)(qrow + 8) * D;
    uint32_t qf[8][4];
    #pragma unroll
    for (int k8 = 0; k8 < 8; k8++) {
        qf[k8][0] = f2u(qr0[k8 * 8 + tg]);
        qf[k8][1] = f2u(qr8[k8 * 8 + tg]);
        qf[k8][2] = f2u(qr0[k8 * 8 + tg + 4]);
        qf[k8][3] = f2u(qr8[k8 * 8 + tg + 4]);
    }

    float m0v = -1e30f, m1v = -1e30f, l0 = 0.f, l1 = 0.f;
    float o[8][4] = {};

    auto load_kv = [&](int kt, int st) {
        float* K = stage0 + st * STAGE;
        float* V = K + 64 * KST;
        #pragma unroll
        for (int i = 0; i < 8; i++) {
            int f = t + i * 128;              // 0..1023
            int r = f >> 4;                   // 0..63
            int c4 = (f & 15) * 4;            // 0..60
            cp16(&K[r * KST + c4], &kb[(size_t)(kt + r) * D + c4]);
            cp16(&V[r * VST + c4], &vb[(size_t)(kt + r) * D + c4]);
        }
        cp_commit();
    };

    constexpr int NT = S / 64;   // 32 key tiles
    load_kv(0, 0);

    for (int it = 0; it < NT; it++) {
        const int st = it & 1;
        if (it + 1 < NT) {
            load_kv((it + 1) * 64, st ^ 1);
            cp_wait<1>();
        } else {
            cp_wait<0>();
        }
        __syncthreads();

        float* K = stage0 + st * STAGE;
        float* V = K + 64 * KST;

        // Phase 1: scores (16 q-rows x 64 keys per warp), B frags from K tile
        float sc[8][4] = {};
        #pragma unroll
        for (int k8 = 0; k8 < 8; k8++) {
            #pragma unroll
            for (int nt = 0; nt < 8; nt++) {
                uint32_t b0 = f2u(K[(nt * 8 + g) * KST + k8 * 8 + tg]);
                uint32_t b1 = f2u(K[(nt * 8 + g) * KST + k8 * 8 + tg + 4]);
                mma_tf32(sc[nt], qf[k8][0], qf[k8][1], qf[k8][2], qf[k8][3], b0, b1);
            }
        }

        // Scale + online softmax in register fragments
        float mx0 = -1e30f, mx1 = -1e30f;
        #pragma unroll
        for (int nt = 0; nt < 8; nt++) {
            #pragma unroll
            for (int j = 0; j < 4; j++) sc[nt][j] *= 0.125f;
            mx0 = fmaxf(mx0, fmaxf(sc[nt][0], sc[nt][1]));
            mx1 = fmaxf(mx1, fmaxf(sc[nt][2], sc[nt][3]));
        }
        mx0 = fmaxf(mx0, __shfl_xor_sync(0xffffffffu, mx0, 1));
        mx0 = fmaxf(mx0, __shfl_xor_sync(0xffffffffu, mx0, 2));
        mx1 = fmaxf(mx1, __shfl_xor_sync(0xffffffffu, mx1, 1));
        mx1 = fmaxf(mx1, __shfl_xor_sync(0xffffffffu, mx1, 2));

        const float mn0 = fmaxf(m0v, mx0);
        const float mn1 = fmaxf(m1v, mx1);
        const float rs0 = __expf(m0v - mn0);
        const float rs1 = __expf(m1v - mn1);
        m0v = mn0; m1v = mn1;

        const int r0 = warp * 16 + g;
        float s0 = 0.f, s1 = 0.f;
        #pragma unroll
        for (int nt = 0; nt < 8; nt++) {
            float p0 = __expf(sc[nt][0] - mn0);
            float p1 = __expf(sc[nt][1] - mn0);
            float p2 = __expf(sc[nt][2] - mn1);
            float p3 = __expf(sc[nt][3] - mn1);
            s0 += p0 + p1;
            s1 += p2 + p3;
            const int col = nt * 8 + 2 * tg;
            *(float2*)&Ps[r0 * QST + col] = make_float2(p0, p1);
            *(float2*)&Ps[(r0 + 8) * QST + col] = make_float2(p2, p3);
        }
        s0 += __shfl_xor_sync(0xffffffffu, s0, 1);
        s0 += __shfl_xor_sync(0xffffffffu, s0, 2);
        s1 += __shfl_xor_sync(0xffffffffu, s1, 1);
        s1 += __shfl_xor_sync(0xffffffffu, s1, 2);
        l0 = l0 * rs0 + s0;
        l1 = l1 * rs1 + s1;

        // Rescale O accumulators
        #pragma unroll
        for (int nt = 0; nt < 8; nt++) {
            o[nt][0] *= rs0; o[nt][1] *= rs0;
            o[nt][2] *= rs1; o[nt][3] *= rs1;
        }
        __syncwarp();   // P rows are warp-private; warp-scope visibility suffices

        // Phase 2: O += P @ V   (A frags from Ps, B frags from V tile)
        #pragma unroll
        for (int k8 = 0; k8 < 8; k8++) {
            uint32_t a0 = f2u(Ps[r0 * QST + k8 * 8 + tg]);
            uint32_t a1 = f2u(Ps[(r0 + 8) * QST + k8 * 8 + tg]);
            uint32_t a2 = f2u(Ps[r0 * QST + k8 * 8 + tg + 4]);
            uint32_t a3 = f2u(Ps[(r0 + 8) * QST + k8 * 8 + tg + 4]);
            #pragma unroll
            for (int nt = 0; nt < 8; nt++) {
                uint32_t b0 = f2u(V[(k8 * 8 + tg) * VST + nt * 8 + g]);
                uint32_t b1 = f2u(V[(k8 * 8 + tg + 4) * VST + nt * 8 + g]);
                mma_tf32(o[nt], a0, a1, a2, a3, b0, b1);
            }
        }
        __syncthreads();   // protect K/V stage buffer before next prefetch overwrites
    }

    // Epilogue: normalize by l, write out
    const float inv0 = 1.f / l0;
    const float inv1 = 1.f / l1;
    const int row0 = q0 + warp * 16 + g;
    #pragma unroll
    for (int nt = 0; nt < 8; nt++) {
        const int col = nt * 8 + 2 * tg;
        float2 v0 = make_float2(o[nt][0] * inv0, o[nt][1] * inv0);
        float2 v1 = make_float2(o[nt][2] * inv1, o[nt][3] * inv1);
        *(float2*)&ob[(size_t)row0 * D + col] = v0;
        *(float2*)&ob[(size_t)(row0 + 8) * D + col] = v1;
    }
}

// ---------------------------------------------------------------------------
// Kernel 3: residual add + LayerNorm (eps = 1e-6) + affine.  One block per row.
// ---------------------------------------------------------------------------
__global__ __launch_bounds__(256) void ln_kernel(
    const float* __restrict__ resid,
    const float* __restrict__ gamma,
    const float* __restrict__ beta,
    float* __restrict__ out)
{
    const int row = blockIdx.x;
    const int t   = threadIdx.x;

    float4 o4 = *(const float4*)&g_o[(size_t)row * D + t * 4];
    float4 r4 = *(const float4*)&resid[(size_t)row * D + t * 4];
    float4 y;
    y.x = o4.x + r4.x;
    y.y = o4.y + r4.y;
    y.z = o4.z + r4.z;
    y.w = o4.w + r4.w;

    float s  = y.x + y.y + y.z + y.w;
    float sq = y.x * y.x + y.y * y.y + y.z * y.z + y.w * y.w;

    #pragma unroll
    for (int off = 16; off > 0; off >>= 1) {
        s  += __shfl_xor_sync(0xffffffffu, s,  off);
        sq += __shfl_xor_sync(0xffffffffu, sq, off);
    }
    __shared__ float red_s[8], red_q[8], stats[2];
    int wid = t >> 5, lane = t & 31;
    if (lane == 0) { red_s[wid] = s; red_q[wid] = sq; }
    __syncthreads();
    if (t == 0) {
        float ts = 0.f, tq = 0.f;
        #pragma unroll
        for (int i = 0; i < 8; i++) { ts += red_s[i]; tq += red_q[i]; }
        float mu  = ts / (float)D;
        float var = tq / (float)D - mu * mu;
        stats[0] = mu;
        stats[1] = rsqrtf(var + 1e-6f);
    }
    __syncthreads();
    float mu = stats[0], rstd = stats[1];

    float4 g4 = *(const float4*)&gamma[t * 4];
    float4 b4 = *(const float4*)&beta[t * 4];
    float4 outv;
    outv.x = (y.x - mu) * rstd * g4.x + b4.x;
    outv.y = (y.y - mu) * rstd * g4.y + b4.y;
    outv.z = (y.z - mu) * rstd * g4.z + b4.z;
    outv.w = (y.w - mu) * rstd * g4.w + b4.w;
    *(float4*)&out[(size_t)row * D + t * 4] = outv;
}

// ---------------------------------------------------------------------------
extern "C" void kernel_launch(void* const* d_in, const int* in_sizes, int n_in,
                              void* d_out, int out_size)
{
    const float* query = (const float*)d_in[0];
    const float* key_  = (const float*)d_in[1];
    const float* value = (const float*)d_in[2];
    const float* Wq    = (const float*)d_in[3];
    const float* bq    = (const float*)d_in[4];
    const float* Wk    = (const float*)d_in[5];
    const float* bk    = (const float*)d_in[6];
    const float* Wv    = (const float*)d_in[7];
    const float* bv    = (const float*)d_in[8];
    const float* gamma = (const float*)d_in[9];
    const float* beta  = (const float*)d_in[10];
    float* out = (float*)d_out;

    // Opt-in to >48KB dynamic smem (idempotent; no alloc)
    cudaFuncSetAttribute(qkv_gemm_tc, cudaFuncAttributeMaxDynamicSharedMemorySize, QKV_SMEM);
    cudaFuncSetAttribute(attn_tc, cudaFuncAttributeMaxDynamicSharedMemorySize, ATTN_SMEM);

    dim3 gproj(D / 128, M / 128, 3);        // (8, 32, 3)
    qkv_gemm_tc<<<gproj, 256, QKV_SMEM>>>(query, key_, value, Wq, Wk, Wv, bq, bk, bv);

    dim3 gattn(S / 64, B * H);              // (32, 32)
    attn_tc<<<gattn, 128, ATTN_SMEM>>>();

    ln_kernel<<<M, 256>>>(query, gamma, beta, out);
}

// round 12
// speedup vs baseline: 3.9819x; 1.0285x over previous
#include <cuda_runtime.h>
#include <cstdint>

// Problem constants
constexpr int B  = 2;
constexpr int S  = 2048;
constexpr int D  = 1024;
constexpr int H  = 16;
constexpr int DK = 64;
constexpr int M  = B * S;

// Scratch (allocation-free rule: __device__ globals)
__device__ float g_q[M * D];
__device__ float g_k[M * D];
__device__ float g_v[M * D];
__device__ float g_o[M * D];

// ---------------------------------------------------------------------------
// PTX helpers
// ---------------------------------------------------------------------------
__device__ __forceinline__ void mma_tf32(float c[4],
                                         uint32_t a0, uint32_t a1, uint32_t a2, uint32_t a3,
                                         uint32_t b0, uint32_t b1) {
    asm volatile(
        "mma.sync.aligned.m16n8k8.row.col.f32.tf32.tf32.f32 "
        "{%0,%1,%2,%3}, {%4,%5,%6,%7}, {%8,%9}, {%0,%1,%2,%3};\n"
        : "+f"(c[0]), "+f"(c[1]), "+f"(c[2]), "+f"(c[3])
        : "r"(a0), "r"(a1), "r"(a2), "r"(a3), "r"(b0), "r"(b1));
}

__device__ __forceinline__ void ldsm_x4(uint32_t& r0, uint32_t& r1, uint32_t& r2, uint32_t& r3,
                                        uint32_t saddr) {
    asm volatile("ldmatrix.sync.aligned.m8n8.x4.shared.b16 {%0,%1,%2,%3}, [%4];\n"
                 : "=r"(r0), "=r"(r1), "=r"(r2), "=r"(r3) : "r"(saddr));
}

__device__ __forceinline__ void cp16(void* smem_ptr, const void* gptr) {
    uint32_t s = (uint32_t)__cvta_generic_to_shared(smem_ptr);
    asm volatile("cp.async.cg.shared.global [%0], [%1], 16;\n" :: "r"(s), "l"(gptr));
}
__device__ __forceinline__ void cp_commit() { asm volatile("cp.async.commit_group;\n"); }
template <int N>
__device__ __forceinline__ void cp_wait() { asm volatile("cp.async.wait_group %0;\n" :: "n"(N)); }

__device__ __forceinline__ uint32_t f2u(float x) { return __float_as_uint(x); }
__device__ __forceinline__ uint32_t s2u(const void* p) { return (uint32_t)__cvta_generic_to_shared(p); }

// ---------------------------------------------------------------------------
// Kernel 1: QKV projection GEMM on tensor cores (tf32).
// Block tile 128x128, K-step 32, 3-stage cp.async pipeline (dynamic smem).
// 256 threads = 8 warps (2 x 4); warp tile 64x32 (4 m-tiles x 4 n-tiles).
// A-frags via ldmatrix.x4, B-frags scalar LDS (conflict-free pads).
// ---------------------------------------------------------------------------
constexpr int KS  = 32;
constexpr int AST = 36;    // A row pad: 144B rows, 16B-aligned, ldsm rows 4 banks apart
constexpr int BST = 136;   // B row pad: (8tg+g) banks -> conflict-free scalar LDS
constexpr int ASTAGE = 128 * AST;
constexpr int BSTAGE = KS * BST;
constexpr int QKV_STAGE = ASTAGE + BSTAGE;              // 8960 floats
constexpr int QKV_SMEM  = 3 * QKV_STAGE * 4;            // 107520 bytes

__global__ __launch_bounds__(256, 2) void qkv_gemm_tc(
    const float* __restrict__ Xq, const float* __restrict__ Xk, const float* __restrict__ Xv,
    const float* __restrict__ Wq, const float* __restrict__ Wk, const float* __restrict__ Wv,
    const float* __restrict__ bq, const float* __restrict__ bk, const float* __restrict__ bv)
{
    const float* X; const float* W; const float* bias; float* Y;
    if (blockIdx.z == 0)      { X = Xq; W = Wq; bias = bq; Y = g_q; }
    else if (blockIdx.z == 1) { X = Xk; W = Wk; bias = bk; Y = g_k; }
    else                      { X = Xv; W = Wv; bias = bv; Y = g_v; }

    extern __shared__ float qsm[];

    const int t    = threadIdx.x;
    const int lane = t & 31;
    const int warp = t >> 5;
    const int wm   = (warp >> 2) * 64;     // 2 warps along m
    const int wn   = (warp & 3) * 32;      // 4 warps along n
    const int g    = lane >> 2;
    const int tg   = lane & 3;
    const int m0   = blockIdx.y * 128;
    const int n0   = blockIdx.x * 128;

    // ldmatrix lane offsets for A-frags (mat = lane>>3)
    const int matq = lane >> 3;
    const int rowA = (matq & 1) * 8 + (lane & 7);
    const int colA = (matq >> 1) * 4;

    float acc[4][4][4] = {};

    auto load_tiles = [&](int k0, int buf) {
        float* As = qsm + buf * QKV_STAGE;
        float* Bs = As + ASTAGE;
        #pragma unroll
        for (int i = 0; i < 4; i++) {
            int f = t + i * 256;                 // 0..1023
            int r = f >> 3, c4 = (f & 7) * 4;    // A: 128 rows x 32 cols
            cp16(&As[r * AST + c4], &X[(size_t)(m0 + r) * D + k0 + c4]);
        }
        #pragma unroll
        for (int i = 0; i < 4; i++) {
            int f = t + i * 256;
            int r = f >> 5, c4 = (f & 31) * 4;   // B: 32 rows x 128 cols
            cp16(&Bs[r * BST + c4], &W[(size_t)(k0 + r) * D + n0 + c4]);
        }
        cp_commit();
    };

    constexpr int KT = D / KS;   // 32 k-steps
    load_tiles(0, 0);
    load_tiles(KS, 1);

    int buf = 0;
    for (int kt = 0; kt < KT; kt++) {
        if (kt + 2 < KT) load_tiles((kt + 2) * KS, (kt + 2) % 3);
        else             cp_commit();            // keep group count invariant
        cp_wait<2>();
        __syncthreads();

        const float* As = qsm + buf * QKV_STAGE;
        const float* Bs = As + ASTAGE;
        const uint32_t aBase = s2u(As) + ((wm + rowA) * AST + colA) * 4;

        #pragma unroll
        for (int kk = 0; kk < KS; kk += 8) {
            // B fragments first (8 scalar LDS, conflict-free)
            uint32_t bf[4][2];
            #pragma unroll
            for (int nt = 0; nt < 4; nt++) {
                const int col = wn + nt * 8 + g;
                bf[nt][0] = f2u(Bs[(kk + tg) * BST + col]);
                bf[nt][1] = f2u(Bs[(kk + tg + 4) * BST + col]);
            }
            // A fragments per m-tile via ldmatrix, consumed immediately
            #pragma unroll
            for (int mt = 0; mt < 4; mt++) {
                uint32_t a0, a1, a2, a3;
                ldsm_x4(a0, a1, a2, a3, aBase + (mt * 16 * AST + kk) * 4);
                #pragma unroll
                for (int nt = 0; nt < 4; nt++)
                    mma_tf32(acc[mt][nt], a0, a1, a2, a3, bf[nt][0], bf[nt][1]);
            }
        }
        __syncthreads();
        buf = (buf + 1 == 3) ? 0 : buf + 1;
    }

    // Epilogue: + bias, write float2 pairs
    #pragma unroll
    for (int nt = 0; nt < 4; nt++) {
        const int col = n0 + wn + nt * 8 + 2 * tg;
        const float bv0 = bias[col];
        const float bv1 = bias[col + 1];
        #pragma unroll
        for (int mt = 0; mt < 4; mt++) {
            const int row = m0 + wm + mt * 16 + g;
            float2 v0 = make_float2(acc[mt][nt][0] + bv0, acc[mt][nt][1] + bv1);
            float2 v1 = make_float2(acc[mt][nt][2] + bv0, acc[mt][nt][3] + bv1);
            *(float2*)&Y[(size_t)row * D + col] = v0;
            *(float2*)&Y[(size_t)(row + 8) * D + col] = v1;
        }
    }
}

// ---------------------------------------------------------------------------
// Kernel 2: flash attention on tensor cores (tf32), online softmax in C-frags.
// Grid (S/128, B*H), 256 threads = 8 warps; warp owns 16 query rows (q-tile 128).
// Q frags register-resident; K/V double-buffered cp.async; K B-frags and
// P A-frags via ldmatrix.
// ---------------------------------------------------------------------------
constexpr int QTILE = 128;
constexpr int QST = 68;   // P smem stride (272B rows: 16B-aligned, 4-bank row step)
constexpr int KST = 68;   // K smem stride
constexpr int VST = 72;   // V smem stride (8tg+8nt+g banks: conflict-free)
constexpr int STAGE = 64 * KST + 64 * VST;
constexpr int ATTN_SMEM = (QTILE * QST + 2 * STAGE) * 4;   // 106496 bytes

__global__ __launch_bounds__(256, 2) void attn_tc()
{
    extern __shared__ float sm[];
    float* Ps     = sm;                    // QTILE x QST, warp-private row blocks
    float* stage0 = sm + QTILE * QST;

    const int t    = threadIdx.x;
    const int lane = t & 31;
    const int warp = t >> 5;
    const int g    = lane >> 2;
    const int tg   = lane & 3;

    // ldmatrix lane offsets
    const int matq = lane >> 3;
    const int rowP = (matq & 1) * 8 + (lane & 7);     // A-frag pattern (P)
    const int colP = (matq >> 1) * 4;
    const int rowK = ((lane >> 4) & 1) * 8 + (lane & 7);  // B-frag pattern (K)
    const int colK = ((lane >> 3) & 1) * 4;

    const int bh = blockIdx.y;
    const int b  = bh / H;
    const int h  = bh % H;
    const int q0 = blockIdx.x * QTILE;

    const float* qb = g_q + (size_t)b * S * D + h * DK;
    const float* kb = g_k + (size_t)b * S * D + h * DK;
    const float* vb = g_v + (size_t)b * S * D + h * DK;
    float*       ob = g_o + (size_t)b * S * D + h * DK;

    // Q fragments, loaded once straight from gmem (A operand, m16 x k64)
    const int qrow = q0 + warp * 16 + g;
    const float* qr0 = qb + (size_t)qrow * D;
    const float* qr8 = qb + (size_t)(qrow + 8) * D;
    uint32_t qf[8][4];
    #pragma unroll
    for (int k8 = 0; k8 < 8; k8++) {
        qf[k8][0] = f2u(qr0[k8 * 8 + tg]);
        qf[k8][1] = f2u(qr8[k8 * 8 + tg]);
        qf[k8][2] = f2u(qr0[k8 * 8 + tg + 4]);
        qf[k8][3] = f2u(qr8[k8 * 8 + tg + 4]);
    }

    float m0v = -1e30f, m1v = -1e30f, l0 = 0.f, l1 = 0.f;
    float o[8][4] = {};

    auto load_kv = [&](int kt, int st) {
        float* K = stage0 + st * STAGE;
        float* V = K + 64 * KST;
        #pragma unroll
        for (int i = 0; i < 4; i++) {
            int f = t + i * 256;              // 0..1023
            int r = f >> 4;                   // 0..63
            int c4 = (f & 15) * 4;            // 0..60
            cp16(&K[r * KST + c4], &kb[(size_t)(kt + r) * D + c4]);
            cp16(&V[r * VST + c4], &vb[(size_t)(kt + r) * D + c4]);
        }
        cp_commit();
    };

    constexpr int NT = S / 64;   // 32 key tiles
    load_kv(0, 0);

    const int r0 = warp * 16 + g;
    const uint32_t pBase = s2u(Ps) + ((warp * 16 + rowP) * QST + colP) * 4;

    for (int it = 0; it < NT; it++) {
        const int st = it & 1;
        if (it + 1 < NT) {
            load_kv((it + 1) * 64, st ^ 1);
            cp_wait<1>();
        } else {
            cp_wait<0>();
        }
        __syncthreads();

        float* K = stage0 + st * STAGE;
        float* V = K + 64 * KST;
        const uint32_t kBase = s2u(K) + (rowK * KST + colK) * 4;

        // Phase 1: scores (16 q-rows x 64 keys per warp); K B-frags via ldmatrix
        float sc[8][4] = {};
        #pragma unroll
        for (int k8 = 0; k8 < 8; k8++) {
            const int kk = k8 * 8;
            #pragma unroll
            for (int p = 0; p < 4; p++) {
                uint32_t kb0, kb1, kb2, kb3;
                ldsm_x4(kb0, kb1, kb2, kb3, kBase + (p * 16 * KST + kk) * 4);
                mma_tf32(sc[2 * p],     qf[k8][0], qf[k8][1], qf[k8][2], qf[k8][3], kb0, kb1);
                mma_tf32(sc[2 * p + 1], qf[k8][0], qf[k8][1], qf[k8][2], qf[k8][3], kb2, kb3);
            }
        }

        // Scale + online softmax in register fragments
        float mx0 = -1e30f, mx1 = -1e30f;
        #pragma unroll
        for (int nt = 0; nt < 8; nt++) {
            #pragma unroll
            for (int j = 0; j < 4; j++) sc[nt][j] *= 0.125f;
            mx0 = fmaxf(mx0, fmaxf(sc[nt][0], sc[nt][1]));
            mx1 = fmaxf(mx1, fmaxf(sc[nt][2], sc[nt][3]));
        }
        mx0 = fmaxf(mx0, __shfl_xor_sync(0xffffffffu, mx0, 1));
        mx0 = fmaxf(mx0, __shfl_xor_sync(0xffffffffu, mx0, 2));
        mx1 = fmaxf(mx1, __shfl_xor_sync(0xffffffffu, mx1, 1));
        mx1 = fmaxf(mx1, __shfl_xor_sync(0xffffffffu, mx1, 2));

        const float mn0 = fmaxf(m0v, mx0);
        const float mn1 = fmaxf(m1v, mx1);
        const float rs0 = __expf(m0v - mn0);
        const float rs1 = __expf(m1v - mn1);
        m0v = mn0; m1v = mn1;

        float s0 = 0.f, s1 = 0.f;
        #pragma unroll
        for (int nt = 0; nt < 8; nt++) {
            float p0 = __expf(sc[nt][0] - mn0);
            float p1 = __expf(sc[nt][1] - mn0);
            float p2 = __expf(sc[nt][2] - mn1);
            float p3 = __expf(sc[nt][3] - mn1);
            s0 += p0 + p1;
            s1 += p2 + p3;
            const int col = nt * 8 + 2 * tg;
            *(float2*)&Ps[r0 * QST + col] = make_float2(p0, p1);
            *(float2*)&Ps[(r0 + 8) * QST + col] = make_float2(p2, p3);
        }
        s0 += __shfl_xor_sync(0xffffffffu, s0, 1);
        s0 += __shfl_xor_sync(0xffffffffu, s0, 2);
        s1 += __shfl_xor_sync(0xffffffffu, s1, 1);
        s1 += __shfl_xor_sync(0xffffffffu, s1, 2);
        l0 = l0 * rs0 + s0;
        l1 = l1 * rs1 + s1;

        // Rescale O accumulators
        #pragma unroll
        for (int nt = 0; nt < 8; nt++) {
            o[nt][0] *= rs0; o[nt][1] *= rs0;
            o[nt][2] *= rs1; o[nt][3] *= rs1;
        }
        __syncwarp();   // P rows are warp-private

        // Phase 2: O += P @ V   (P A-frags via ldmatrix, V scalar LDS)
        #pragma unroll
        for (int k8 = 0; k8 < 8; k8++) {
            const int kk = k8 * 8;
            uint32_t pa0, pa1, pa2, pa3;
            ldsm_x4(pa0, pa1, pa2, pa3, pBase + kk * 4);
            #pragma unroll
            for (int nt = 0; nt < 8; nt++) {
                uint32_t b0 = f2u(V[(kk + tg) * VST + nt * 8 + g]);
                uint32_t b1 = f2u(V[(kk + tg + 4) * VST + nt * 8 + g]);
                mma_tf32(o[nt], pa0, pa1, pa2, pa3, b0, b1);
            }
        }
        __syncthreads();   // protect K/V stage before next prefetch overwrites
    }

    // Epilogue: normalize by l, write out
    const float inv0 = 1.f / l0;
    const float inv1 = 1.f / l1;
    const int row0 = q0 + warp * 16 + g;
    #pragma unroll
    for (int nt = 0; nt < 8; nt++) {
        const int col = nt * 8 + 2 * tg;
        float2 v0 = make_float2(o[nt][0] * inv0, o[nt][1] * inv0);
        float2 v1 = make_float2(o[nt][2] * inv1, o[nt][3] * inv1);
        *(float2*)&ob[(size_t)row0 * D + col] = v0;
        *(float2*)&ob[(size_t)(row0 + 8) * D + col] = v1;
    }
}

// ---------------------------------------------------------------------------
// Kernel 3: residual add + LayerNorm (eps = 1e-6) + affine.  One block per row.
// ---------------------------------------------------------------------------
__global__ __launch_bounds__(256) void ln_kernel(
    const float* __restrict__ resid,
    const float* __restrict__ gamma,
    const float* __restrict__ beta,
    float* __restrict__ out)
{
    const int row = blockIdx.x;
    const int t   = threadIdx.x;

    float4 o4 = *(const float4*)&g_o[(size_t)row * D + t * 4];
    float4 r4 = *(const float4*)&resid[(size_t)row * D + t * 4];
    float4 y;
    y.x = o4.x + r4.x;
    y.y = o4.y + r4.y;
    y.z = o4.z + r4.z;
    y.w = o4.w + r4.w;

    float s  = y.x + y.y + y.z + y.w;
    float sq = y.x * y.x + y.y * y.y + y.z * y.z + y.w * y.w;

    #pragma unroll
    for (int off = 16; off > 0; off >>= 1) {
        s  += __shfl_xor_sync(0xffffffffu, s,  off);
        sq += __shfl_xor_sync(0xffffffffu, sq, off);
    }
    __shared__ float red_s[8], red_q[8], stats[2];
    int wid = t >> 5, lane = t & 31;
    if (lane == 0) { red_s[wid] = s; red_q[wid] = sq; }
    __syncthreads();
    if (t == 0) {
        float ts = 0.f, tq = 0.f;
        #pragma unroll
        for (int i = 0; i < 8; i++) { ts += red_s[i]; tq += red_q[i]; }
        float mu  = ts / (float)D;
        float var = tq / (float)D - mu * mu;
        stats[0] = mu;
        stats[1] = rsqrtf(var + 1e-6f);
    }
    __syncthreads();
    float mu = stats[0], rstd = stats[1];

    float4 g4 = *(const float4*)&gamma[t * 4];
    float4 b4 = *(const float4*)&beta[t * 4];
    float4 outv;
    outv.x = (y.x - mu) * rstd * g4.x + b4.x;
    outv.y = (y.y - mu) * rstd * g4.y + b4.y;
    outv.z = (y.z - mu) * rstd * g4.z + b4.z;
    outv.w = (y.w - mu) * rstd * g4.w + b4.w;
    *(float4*)&out[(size_t)row * D + t * 4] = outv;
}

// ---------------------------------------------------------------------------
extern "C" void kernel_launch(void* const* d_in, const int* in_sizes, int n_in,
                              void* d_out, int out_size)
{
    const float* query = (const float*)d_in[0];
    const float* key_  = (const float*)d_in[1];
    const float* value = (const float*)d_in[2];
    const float* Wq    = (const float*)d_in[3];
    const float* bq    = (const float*)d_in[4];
    const float* Wk    = (const float*)d_in[5];
    const float* bk    = (const float*)d_in[6];
    const float* Wv    = (const float*)d_in[7];
    const float* bv    = (const float*)d_in[8];
    const float* gamma = (const float*)d_in[9];
    const float* beta  = (const float*)d_in[10];
    float* out = (float*)d_out;

    // Opt-in to >48KB dynamic smem (idempotent; no alloc)
    cudaFuncSetAttribute(qkv_gemm_tc, cudaFuncAttributeMaxDynamicSharedMemorySize, QKV_SMEM);
    cudaFuncSetAttribute(attn_tc, cudaFuncAttributeMaxDynamicSharedMemorySize, ATTN_SMEM);

    dim3 gproj(D / 128, M / 128, 3);        // (8, 32, 3)
    qkv_gemm_tc<<<gproj, 256, QKV_SMEM>>>(query, key_, value, Wq, Wk, Wv, bq, bk, bv);

    dim3 gattn(S / QTILE, B * H);           // (16, 32)
    attn_tc<<<gattn, 256, ATTN_SMEM>>>();

    ln_kernel<<<M, 256>>>(query, gamma, beta, out);
}